// round 13
// baseline (speedup 1.0000x reference)
#include <cuda_runtime.h>
#include <cuda_bf16.h>
#include <math.h>

#define NN    50000
#define NFEAT 256
#define NHID  128
#define NA    32
#define NP    4
#define NBLKS 391              // ceil(NN/128)
#define NSLAB (NBLKS * 8)      // 128-col split tensors: 8 slabs per row-block

// ---------------- scratch (device globals; no allocation allowed) ----------------
// split-format activations: [nblk][kt][ H:1024 | L:1024 ] u32 slabs
__device__ unsigned g_tmp_s[NSLAB * 2048];
__device__ unsigned g_h_s  [NSLAB * 2048];
__device__ unsigned g_xcA_s[NSLAB * 2048];
__device__ unsigned g_z_s  [NSLAB * 2048];
__device__ unsigned g_ws   [80 * 2048];      // pre-split weights (80 slabs)
// fp32 tensors
__device__ float g_hx[NN*NP*NHID];           // [n][p*128+j]
__device__ float g_haB[NP*NA*NHID];
__device__ float g_attn[NN*NA];
__device__ float g_rowsum[NN];
__device__ float g_colsum[NA];
__device__ float g_support[NN*NHID];
__device__ float g_U[NA*NHID];
__device__ float g_xcB[NN*NHID];
__device__ float g_t1[NN*NHID];

// ---------------- packed fp32x2 helpers (Blackwell f32x2 pipe) --------------------
__device__ __forceinline__ void fadd2(float& d0, float& d1,
                                      float a0, float a1, float b0, float b1)
{
    asm("{.reg .b64 ra,rb,rd;\n\t"
        "mov.b64 ra,{%2,%3}; mov.b64 rb,{%4,%5};\n\t"
        "add.rn.f32x2 rd,ra,rb;\n\t"
        "mov.b64 {%0,%1},rd;}"
        : "=f"(d0), "=f"(d1) : "f"(a0), "f"(a1), "f"(b0), "f"(b1));
}
__device__ __forceinline__ void ffma2(float& d0, float& d1,
                                      float a0, float a1, float b0, float b1)
{
    asm("{.reg .b64 ra,rb,rc,rd;\n\t"
        "mov.b64 ra,{%2,%3}; mov.b64 rb,{%4,%5}; mov.b64 rc,{%0,%1};\n\t"
        "fma.rn.f32x2 rd,ra,rb,rc;\n\t"
        "mov.b64 {%0,%1},rd;}"
        : "+f"(d0), "+f"(d1) : "f"(a0), "f"(a1), "f"(b0), "f"(b1));
}

// ---------------- bf16 split helpers ---------------------------------------------
__device__ __forceinline__ void mma_bf16(float* d, const unsigned* a, const unsigned* b)
{
    asm volatile(
        "mma.sync.aligned.m16n8k16.row.col.f32.bf16.bf16.f32 "
        "{%0,%1,%2,%3}, {%4,%5,%6,%7}, {%8,%9}, {%0,%1,%2,%3};\n"
        : "+f"(d[0]), "+f"(d[1]), "+f"(d[2]), "+f"(d[3])
        : "r"(a[0]), "r"(a[1]), "r"(a[2]), "r"(a[3]),
          "r"(b[0]), "r"(b[1]));
}
// pack two floats to bf16x2: first arg -> bits[0:16) (even k), second -> [16:32)
__device__ __forceinline__ unsigned bpack(float lo_elem, float hi_elem) {
    unsigned r;
    asm("cvt.rn.bf16x2.f32 %0, %1, %2;" : "=r"(r) : "f"(hi_elem), "f"(lo_elem));
    return r;
}
__device__ __forceinline__ void bsplit(float v, float& hf, float& lf) {
    hf = __bfloat162float(__float2bfloat16(v));
    lf = v - hf;
}
__device__ __forceinline__ float bf_lo(unsigned u) { return __uint_as_float(u << 16); }
__device__ __forceinline__ float bf_hi(unsigned u) { return __uint_as_float(u & 0xffff0000u); }

// read 4 consecutive cols (c4*4 .. +3) of row (nblk,m) from a 128-col split tensor
__device__ __forceinline__ float4 load_split4(const unsigned* __restrict__ act,
                                              int nblk, int c4, int m)
{
    const int kp0 = c4 * 2;
    const int kt = kp0 >> 3, kpl0 = kp0 & 7, kpl1 = kpl0 + 1;
    const unsigned* slab = act + ((size_t)nblk * 8 + kt) * 2048;
    const int i0 = kpl0 * 128 + (m ^ (8 * (kpl0 & 3)));
    const int i1 = kpl1 * 128 + (m ^ (8 * (kpl1 & 3)));
    unsigned h0 = slab[i0], l0 = slab[i0 + 1024];
    unsigned h1 = slab[i1], l1 = slab[i1 + 1024];
    float4 r;
    r.x = bf_lo(h0) + bf_lo(l0);  r.y = bf_hi(h0) + bf_hi(l0);
    r.z = bf_lo(h1) + bf_lo(l1);  r.w = bf_hi(h1) + bf_hi(l1);
    return r;
}

// ---------------- weight prep: fp32 [K][128] -> split slabs ----------------------
// slab map: [0,16) im_w1, [16,24) im_w2, [24,56) Wx[p] (8 each), [56,72) enc (8 each),
//           [72,80) cls_w1
__global__ void wprep_kernel(const float* __restrict__ im_w1,
                             const float* __restrict__ im_w2,
                             const float* __restrict__ ml_w1,
                             const float* __restrict__ enc_w,
                             const float* __restrict__ cls_w1,
                             unsigned* __restrict__ ws)
{
    const int s = blockIdx.x, n = threadIdx.x;
    const float* W; int kt;
    if (s < 16)      { W = im_w1;                               kt = s; }
    else if (s < 24) { W = im_w2;                               kt = s - 16; }
    else if (s < 56) { int q = s - 24; W = ml_w1 + (q >> 3) * 2 * NHID * NHID; kt = q & 7; }
    else if (s < 72) { int q = s - 56; W = enc_w + (q >> 3) * NHID * NHID;     kt = q & 7; }
    else             { W = cls_w1;                              kt = s - 72; }
    unsigned* slab = ws + (size_t)s * 2048;
    #pragma unroll
    for (int kl = 0; kl < 16; kl += 2) {
        float v0 = W[(size_t)(kt * 16 + kl)     * 128 + n];
        float v1 = W[(size_t)(kt * 16 + kl + 1) * 128 + n];
        float h0, l0, h1, l1;
        bsplit(v0, h0, l0); bsplit(v1, h1, l1);
        int kpl = kl >> 1;
        int idx = kpl * 128 + (n ^ (8 * (kpl & 3)));
        slab[idx]        = bpack(h0, h1);
        slab[1024 + idx] = bpack(l0, l1);
    }
}

// ================= BF16 tensor-core GEMM, split-3, pre-split operands ============
// Block 128x128, BK=16, 512 thr, 16 warps (4m x 4n), warp tile 32x32.
// smem per operand per stage: [kpl 0..7][x 0..127] swizzled, H plane then L plane.
// ASPLIT: 0 = A fp32 (convert in kernel), 1 = A pre-split slabs
// OUTFMT: 0 = C fp32 (ldc), 1 = C split slabs (ldc16 slabs per row-block)

template<int ACT, int ASPLIT, int OUTFMT>
__global__ __launch_bounds__(512, 1) void tgemm_kernel(
    const float* __restrict__ Af, const unsigned* __restrict__ Au,
    const unsigned* __restrict__ Bw,
    const float* __restrict__ bias, const float* __restrict__ alpha,
    float* __restrict__ Cf, unsigned* __restrict__ Cu,
    int M, int KT, int lda, int bstride_u, int ldc, int ldc16)
{
    __shared__ unsigned smA[2 * 2048];
    __shared__ unsigned smB[2 * 2048];

    const int tid = threadIdx.x, lane = tid & 31, warp = tid >> 5;
    const int wm = warp & 3, wn = warp >> 2;
    const int g = lane >> 2, t = lane & 3;
    const int by = blockIdx.y * 128;
    const unsigned* Bbase = Bw + (size_t)blockIdx.x * bstride_u;
    const unsigned* Abase = Au + (size_t)blockIdx.y * KT * 2048;
    const int colbase = blockIdx.x * 128;

    // ASPLIT=0 A mapping (one float4/thread per stage)
    const int arow = tid >> 2, akq = (tid & 3) * 4;
    const int kp0 = (tid & 3) * 2, kp1i = kp0 + 1;
    const int asw0 = arow ^ (8 * (kp0 & 3)), asw1 = arow ^ (8 * (kp1i & 3));
    const bool arow_ok = (by + arow) < M;
    const float* aptr = Af + (size_t)(by + arow) * lda + akq;

    float acc[2][4][4];
    #pragma unroll
    for (int mt = 0; mt < 2; mt++)
        #pragma unroll
        for (int nt = 0; nt < 4; nt++)
            #pragma unroll
            for (int j = 0; j < 4; j++) acc[mt][nt][j] = 0.f;

    // ---- fill stage 0 ----
    if (ASPLIT) {
        *(uint4*)(smA + tid * 4) = *(const uint4*)(Abase + tid * 4);
    } else {
        float4 a0 = make_float4(0, 0, 0, 0);
        if (arow_ok) a0 = *(const float4*)(aptr);
        float h0,l0,h1,l1,h2,l2,h3,l3;
        bsplit(a0.x,h0,l0); bsplit(a0.y,h1,l1); bsplit(a0.z,h2,l2); bsplit(a0.w,h3,l3);
        smA[kp0 * 128 + asw0]         = bpack(h0, h1);
        smA[1024 + kp0 * 128 + asw0]  = bpack(l0, l1);
        smA[kp1i * 128 + asw1]        = bpack(h2, h3);
        smA[1024 + kp1i * 128 + asw1] = bpack(l2, l3);
    }
    *(uint4*)(smB + tid * 4) = *(const uint4*)(Bbase + tid * 4);
    __syncthreads();

    const int swz = 8 * t;

    for (int kt = 0; kt < KT; kt++) {
        const int cur = kt & 1, nxt = cur ^ 1;
        uint4 av, bv; float4 pa;
        const bool hn = (kt + 1) < KT;
        if (hn) {
            if (ASPLIT) av = *(const uint4*)(Abase + (size_t)(kt + 1) * 2048 + tid * 4);
            else {
                pa = make_float4(0, 0, 0, 0);
                if (arow_ok) pa = *(const float4*)(aptr + (kt + 1) * 16);
            }
            bv = *(const uint4*)(Bbase + (size_t)(kt + 1) * 2048 + tid * 4);
        }

        // ---- fragments + MMA (one m16n8k16 slab covers BK=16) ----
        unsigned ahi[2][4], alo[2][4];
        #pragma unroll
        for (int mt = 0; mt < 2; mt++) {
            const int mb = wm * 32 + mt * 16;
            #pragma unroll
            for (int j = 0; j < 4; j++) {
                const int kp = t + (j >> 1) * 4;
                const int m = (mb + g + (j & 1) * 8) ^ swz;
                const int ix = cur * 2048 + kp * 128 + m;
                ahi[mt][j] = smA[ix];
                alo[mt][j] = smA[ix + 1024];
            }
        }
        unsigned bhi[4][2], blo[4][2];
        #pragma unroll
        for (int nt = 0; nt < 4; nt++) {
            const int nb = (wn * 32 + nt * 8 + g) ^ swz;
            #pragma unroll
            for (int j = 0; j < 2; j++) {
                const int kp = t + j * 4;
                const int ix = cur * 2048 + kp * 128 + nb;
                bhi[nt][j] = smB[ix];
                blo[nt][j] = smB[ix + 1024];
            }
        }
        #pragma unroll
        for (int mt = 0; mt < 2; mt++)
            #pragma unroll
            for (int nt = 0; nt < 4; nt++) {
                mma_bf16(acc[mt][nt], ahi[mt], bhi[nt]);
                mma_bf16(acc[mt][nt], alo[mt], bhi[nt]);
                mma_bf16(acc[mt][nt], ahi[mt], blo[nt]);
            }

        if (hn) {
            if (ASPLIT) {
                *(uint4*)(smA + nxt * 2048 + tid * 4) = av;
            } else {
                float h0,l0,h1,l1,h2,l2,h3,l3;
                bsplit(pa.x,h0,l0); bsplit(pa.y,h1,l1);
                bsplit(pa.z,h2,l2); bsplit(pa.w,h3,l3);
                smA[nxt * 2048 + kp0 * 128 + asw0]         = bpack(h0, h1);
                smA[nxt * 2048 + 1024 + kp0 * 128 + asw0]  = bpack(l0, l1);
                smA[nxt * 2048 + kp1i * 128 + asw1]        = bpack(h2, h3);
                smA[nxt * 2048 + 1024 + kp1i * 128 + asw1] = bpack(l2, l3);
            }
            *(uint4*)(smB + nxt * 2048 + tid * 4) = bv;
        }
        __syncthreads();
    }

    // ---- epilogue ----
    #pragma unroll
    for (int mt = 0; mt < 2; mt++) {
        const int ml0 = wm * 32 + mt * 16 + g;       // local m, row = by + ml0
        #pragma unroll
        for (int nt = 0; nt < 4; nt++) {
            const int cl = wn * 32 + nt * 8 + 2 * t;
            float b0 = 0.f, b1 = 0.f;
            if (bias) { b0 = bias[cl]; b1 = bias[cl + 1]; }
            float v0 = acc[mt][nt][0] + b0;
            float v1 = acc[mt][nt][1] + b1;
            float v2 = acc[mt][nt][2] + b0;
            float v3 = acc[mt][nt][3] + b1;
            if (ACT == 1) {
                v0 = fmaxf(v0, 0.f); v1 = fmaxf(v1, 0.f);
                v2 = fmaxf(v2, 0.f); v3 = fmaxf(v3, 0.f);
            }
            if (ACT == 2) {
                float a0 = alpha[cl], a1 = alpha[cl + 1];
                v0 = v0 > 0.f ? v0 : a0 * v0;
                v1 = v1 > 0.f ? v1 : a1 * v1;
                v2 = v2 > 0.f ? v2 : a0 * v2;
                v3 = v3 > 0.f ? v3 : a1 * v3;
            }
            if (OUTFMT == 0) {
                const int row0 = by + ml0;
                if (row0 < M)
                    *(float2*)(Cf + (size_t)row0 * ldc + colbase + cl) = make_float2(v0, v1);
                if (row0 + 8 < M)
                    *(float2*)(Cf + (size_t)(row0 + 8) * ldc + colbase + cl) = make_float2(v2, v3);
            } else {
                const int kp = (colbase + cl) >> 1;
                const int kt_o = kp >> 3, kpl = kp & 7;
                unsigned* slab = Cu + ((size_t)blockIdx.y * ldc16 + kt_o) * 2048;
                float h0,l0,h1,l1;
                bsplit(v0,h0,l0); bsplit(v1,h1,l1);
                int i0 = kpl * 128 + (ml0 ^ (8 * (kpl & 3)));
                slab[i0]        = bpack(h0, h1);
                slab[i0 + 1024] = bpack(l0, l1);
                bsplit(v2,h0,l0); bsplit(v3,h1,l1);
                int i1 = kpl * 128 + ((ml0 + 8) ^ (8 * (kpl & 3)));
                slab[i1]        = bpack(h0, h1);
                slab[i1 + 1024] = bpack(l0, l1);
            }
        }
    }
}

// ---------------- haB[p][a][j] = (anchors @ Wa[p])[a][j] + ml_b1[p][j], swizzled --
__global__ void hab_kernel(const float* __restrict__ anchors,
                           const float* __restrict__ ml_w1,
                           const float* __restrict__ ml_b1,
                           float* __restrict__ haB)
{
    int a = blockIdx.x, p = blockIdx.y, j = threadIdx.x;
    __shared__ float anc[NHID];
    anc[j] = anchors[a * NHID + j];
    __syncthreads();
    const float* Wa = ml_w1 + ((size_t)p * 2 * NHID + NHID) * NHID;
    float acc = ml_b1[p * NHID + j];
    for (int k = 0; k < NHID; k++)
        acc = fmaf(anc[k], Wa[(size_t)k * NHID + j], acc);
    int slot = ((j >> 2) ^ a) & 31;
    haB[((p * NA + a) * 32 + slot) * 4 + (j & 3)] = acc;
}

// ---------------- fused attention with packed f32x2 inner loop -------------------
__global__ __launch_bounds__(256) void attn_kernel(
    const float* __restrict__ hx, const float* __restrict__ haB,
    const float* __restrict__ ml_w2, const float* __restrict__ ml_b2,
    float* __restrict__ attn, float* __restrict__ rowsum, float* __restrict__ colsum)
{
    extern __shared__ float sm[];
    float* hxs  = sm;              // 8192 floats
    float* haBs = sm + 8192;       // 16384 floats
    float* w2s  = sm + 24576;      // 512 floats
    float* sAtt = sm + 25088;      // 512 floats

    const int tid = threadIdx.x;
    const int a = tid & 31, p = (tid >> 5) & 3, r = tid >> 7;
    const int node0 = blockIdx.x * 16;

    const float4* hxg = (const float4*)(hx + (size_t)node0 * NP * NHID);
    float4* hxsv = (float4*)hxs;
    for (int i = tid; i < 2048; i += 256) hxsv[i] = hxg[i];
    const float4* hbg = (const float4*)haB;
    float4* hbv = (float4*)haBs;
    for (int i = tid; i < 4096; i += 256) hbv[i] = hbg[i];
    for (int i = tid; i < 512; i += 256) w2s[i] = ml_w2[i];
    for (int i = tid; i < 512; i += 256) sAtt[i] = 0.f;
    __syncthreads();

    const float4* hxv = (const float4*)hxs;
    const float4* hav = (const float4*)haBs;
    const float4* w2v = (const float4*)w2s;
    const int n0 = r * 8;
    const float4* myhx = hxv + n0 * 128 + p * 32;
    const float4* myha = hav + (p * 32 + a) * 32;
    const float4* myw  = w2v + p * 32;

    float acc0[8], acc1[8], acc2[8], acc3[8];
    #pragma unroll
    for (int n = 0; n < 8; n++) { acc0[n]=0.f; acc1[n]=0.f; acc2[n]=0.f; acc3[n]=0.f; }

    #pragma unroll 2
    for (int j4 = 0; j4 < 32; j4++) {
        float4 ha = myha[(j4 ^ a) & 31];
        float4 w  = myw[j4];
        #pragma unroll
        for (int n = 0; n < 8; n++) {
            float4 hh = myhx[n * 128 + j4];
            float t0, t1, t2, t3;
            fadd2(t0, t1, hh.x, hh.y, ha.x, ha.y);
            fadd2(t2, t3, hh.z, hh.w, ha.z, ha.w);
            t0 = fmaxf(t0, 0.f); t1 = fmaxf(t1, 0.f);
            t2 = fmaxf(t2, 0.f); t3 = fmaxf(t3, 0.f);
            ffma2(acc0[n], acc1[n], t0, t1, w.x, w.y);
            ffma2(acc2[n], acc3[n], t2, t3, w.z, w.w);
        }
    }
    const float b2p = ml_b2[p];
    #pragma unroll
    for (int n = 0; n < 8; n++) {
        float av = (acc0[n] + acc1[n]) + (acc2[n] + acc3[n]);
        float s = 1.f / (1.f + __expf(-(av + b2p)));
        atomicAdd(&sAtt[(n0 + n) * NA + a], s);
    }
    __syncthreads();

    for (int i = tid; i < 512; i += 256) attn[(size_t)node0 * NA + i] = sAtt[i];
    if (tid < 16) {
        float s = 0.f;
        #pragma unroll
        for (int aa = 0; aa < NA; aa++) s += sAtt[tid * NA + aa];
        rowsum[node0 + tid] = s;
    }
    if (tid < NA) {
        float s = 0.f;
        #pragma unroll
        for (int n = 0; n < 16; n++) s += sAtt[n * NA + tid];
        atomicAdd(&colsum[tid], s);
    }
}

// ---------------- U[a][j] += sum_n attn[n][a] * support[n][j] (split-K + atomics) -
__global__ __launch_bounds__(256) void agg_kernel(
    const float* __restrict__ attn, const float* __restrict__ support,
    float* __restrict__ U, int N)
{
    __shared__ float sA[32][32];
    const int tid = threadIdx.x;
    const int j = tid & 127, half = tid >> 7;
    const int node0 = blockIdx.x * 256;
    float acc[16];
    #pragma unroll
    for (int i = 0; i < 16; i++) acc[i] = 0.f;

    for (int base = 0; base < 256; base += 32) {
        __syncthreads();
        for (int idx = tid; idx < 1024; idx += 256) {
            int nn = idx >> 5, aa = idx & 31;
            int n = node0 + base + nn;
            sA[nn][aa] = (n < N) ? attn[(size_t)n * NA + aa] : 0.f;
        }
        __syncthreads();
        for (int nn = 0; nn < 32; nn++) {
            int n = node0 + base + nn;
            float s = (n < N) ? support[(size_t)n * NHID + j] : 0.f;
            #pragma unroll
            for (int i = 0; i < 16; i++)
                acc[i] = fmaf(s, sA[nn][half * 16 + i], acc[i]);
        }
    }
    #pragma unroll
    for (int i = 0; i < 16; i++)
        atomicAdd(&U[(half * 16 + i) * NHID + j], acc[i]);
}

// ---------------- xc[n][j] = relu( invr * sum_a attn[n][a]*(U[a][j]/colsum[a]) + b[j] )
// SPLIT=1: write split-format (for next GEMM's A); SPLIT=0: write fp32
template<int SPLIT>
__global__ __launch_bounds__(128) void xc_kernel(
    const float* __restrict__ attn, const float* __restrict__ rowsum,
    const float* __restrict__ colsum, const float* __restrict__ U,
    const float* __restrict__ bias, float* __restrict__ xcF,
    unsigned* __restrict__ xcS, int N)
{
    __shared__ float Us[NA * NHID];
    __shared__ float incs[NA];
    __shared__ float wa[4][NA];
    const int tid = threadIdx.x;
    if (tid < NA) incs[tid] = 1.f / fmaxf(colsum[tid], 1e-12f);
    __syncthreads();
    for (int idx = tid; idx < NA * NHID; idx += 128)
        Us[idx] = U[idx] * incs[idx >> 7];
    const float bj = bias[tid];
    const int node0 = blockIdx.x * 32;
    for (int nb = 0; nb < 32; nb += 4) {
        __syncthreads();
        {
            int nn = tid >> 5, aa = tid & 31;
            int node = node0 + nb + nn;
            wa[nn][aa] = (node < N) ? attn[(size_t)node * NA + aa] : 0.f;
        }
        __syncthreads();
        #pragma unroll
        for (int nn = 0; nn < 4; nn++) {
            int node = node0 + nb + nn;
            if (node >= N) break;
            float invr = 1.f / fmaxf(rowsum[node], 1e-12f);
            float acc = 0.f;
            #pragma unroll
            for (int a = 0; a < NA; a++)
                acc = fmaf(wa[nn][a], Us[a * NHID + tid], acc);
            float v = fmaxf(acc * invr + bj, 0.f);
            if (SPLIT) {
                float vn = __shfl_down_sync(0xffffffffu, v, 1);
                if (!(tid & 1)) {
                    int kp = tid >> 1, kt = kp >> 3, kpl = kp & 7;
                    int ml = node & 127;
                    unsigned* slab = xcS + ((size_t)(node >> 7) * 8 + kt) * 2048;
                    int i0 = kpl * 128 + (ml ^ (8 * (kpl & 3)));
                    float h0,l0,h1,l1;
                    bsplit(v, h0, l0); bsplit(vn, h1, l1);
                    slab[i0]        = bpack(h0, h1);
                    slab[i0 + 1024] = bpack(l0, l1);
                }
            } else {
                xcF[(size_t)node * NHID + tid] = v;
            }
        }
    }
}

// ---------------- z = LN(xc + h) * g + b ; warp per node --------------------------
// reads xc fp32 + h split; writes out_z fp32 AND z split (for cls GEMM)
__global__ __launch_bounds__(256) void ln_kernel(
    const float* __restrict__ xc, const unsigned* __restrict__ hS,
    const float* __restrict__ g, const float* __restrict__ b,
    float* __restrict__ zout, unsigned* __restrict__ zS, int N)
{
    const int warp = threadIdx.x >> 5, lane = threadIdx.x & 31;
    const int node = blockIdx.x * 8 + warp;
    if (node >= N) return;
    const int nblk = node >> 7, m = node & 127;
    float4 hb = load_split4(hS, nblk, lane, m);
    float4 xa = ((const float4*)(xc + (size_t)node * NHID))[lane];
    float4 z = make_float4(xa.x + hb.x, xa.y + hb.y, xa.z + hb.z, xa.w + hb.w);
    float s1 = z.x + z.y + z.z + z.w;
    float s2 = z.x * z.x + z.y * z.y + z.z * z.z + z.w * z.w;
    #pragma unroll
    for (int o = 16; o > 0; o >>= 1) {
        s1 += __shfl_xor_sync(0xffffffffu, s1, o);
        s2 += __shfl_xor_sync(0xffffffffu, s2, o);
    }
    const float mu = s1 * (1.f / 128.f);
    const float var = s2 * (1.f / 128.f) - mu * mu;
    const float rs = rsqrtf(var + 1e-5f);
    float4 g4 = ((const float4*)g)[lane];
    float4 b4 = ((const float4*)b)[lane];
    float4 o4;
    o4.x = (z.x - mu) * rs * g4.x + b4.x;
    o4.y = (z.y - mu) * rs * g4.y + b4.y;
    o4.z = (z.z - mu) * rs * g4.z + b4.z;
    o4.w = (z.w - mu) * rs * g4.w + b4.w;
    ((float4*)(zout + (size_t)node * NHID))[lane] = o4;

    // split write: cols 4*lane .. +3 -> kps 2*lane, 2*lane+1
    const int kp0 = lane * 2, kt = kp0 >> 3, kpl0 = kp0 & 7, kpl1 = kpl0 + 1;
    unsigned* slab = zS + ((size_t)nblk * 8 + kt) * 2048;
    float h0,l0,h1,l1;
    bsplit(o4.x, h0, l0); bsplit(o4.y, h1, l1);
    int i0 = kpl0 * 128 + (m ^ (8 * (kpl0 & 3)));
    slab[i0]        = bpack(h0, h1);
    slab[i0 + 1024] = bpack(l0, l1);
    bsplit(o4.z, h0, l0); bsplit(o4.w, h1, l1);
    int i1 = kpl1 * 128 + (m ^ (8 * (kpl1 & 3)));
    slab[i1]        = bpack(h0, h1);
    slab[i1 + 1024] = bpack(l0, l1);
}

// ---------------- pred[n][0..1] = t1[n] @ cls_w2 + cls_b2 ; warp per node ---------
__global__ __launch_bounds__(256) void pred_kernel(
    const float* __restrict__ t1, const float* __restrict__ cls_w2,
    const float* __restrict__ cls_b2, float* __restrict__ pred, int N)
{
    const int warp = threadIdx.x >> 5, lane = threadIdx.x & 31;
    const int node = blockIdx.x * 8 + warp;
    if (node >= N) return;
    float4 t = ((const float4*)(t1 + (size_t)node * NHID))[lane];
    const float4* wv = (const float4*)cls_w2;
    float4 wA = wv[lane * 2], wB = wv[lane * 2 + 1];
    float a0 = t.x * wA.x + t.y * wA.z + t.z * wB.x + t.w * wB.z;
    float a1 = t.x * wA.y + t.y * wA.w + t.z * wB.y + t.w * wB.w;
    #pragma unroll
    for (int o = 16; o > 0; o >>= 1) {
        a0 += __shfl_xor_sync(0xffffffffu, a0, o);
        a1 += __shfl_xor_sync(0xffffffffu, a1, o);
    }
    if (lane == 0) {
        pred[(size_t)node * 2 + 0] = a0 + cls_b2[0];
        pred[(size_t)node * 2 + 1] = a1 + cls_b2[1];
    }
}

// ---------------- anchors: copy anchor_vec + anchor classifier --------------------
__global__ __launch_bounds__(128) void anchor_kernel(
    const float* __restrict__ anchors, const float* __restrict__ cls_w1,
    const float* __restrict__ cls_b1, const float* __restrict__ prelu,
    const float* __restrict__ cls_w2, const float* __restrict__ cls_b2,
    float* __restrict__ avec, float* __restrict__ alog)
{
    __shared__ float t1s[NA * NHID];
    const int j = threadIdx.x;
    for (int idx = j; idx < NA * NHID; idx += 128) avec[idx] = anchors[idx];
    for (int aa = 0; aa < NA; aa++) {
        float acc = cls_b1[j];
        for (int k = 0; k < NHID; k++)
            acc = fmaf(anchors[aa * NHID + k], cls_w1[k * NHID + j], acc);
        t1s[aa * NHID + j] = acc > 0.f ? acc : prelu[j] * acc;
    }
    __syncthreads();
    if (j < 64) {
        int a = j >> 1, c = j & 1;
        float acc = cls_b2[c];
        for (int k = 0; k < NHID; k++)
            acc = fmaf(t1s[a * NHID + k], cls_w2[k * 2 + c], acc);
        alog[j] = acc;
    }
}

// =================================================================================
extern "C" void kernel_launch(void* const* d_in, const int* in_sizes, int n_in,
                              void* d_out, int out_size)
{
    const float* x       = (const float*)d_in[0];
    const float* im_w1   = (const float*)d_in[1];
    const float* im_b1   = (const float*)d_in[2];
    const float* im_w2   = (const float*)d_in[3];
    const float* im_b2   = (const float*)d_in[4];
    const float* anchors = (const float*)d_in[5];
    const float* ml_w1   = (const float*)d_in[6];
    const float* ml_b1   = (const float*)d_in[7];
    const float* ml_w2   = (const float*)d_in[8];
    const float* ml_b2   = (const float*)d_in[9];
    const float* enc_w   = (const float*)d_in[10];
    const float* enc_b   = (const float*)d_in[11];
    const float* ln_g    = (const float*)d_in[12];
    const float* ln_b    = (const float*)d_in[13];
    const float* cls_w1  = (const float*)d_in[14];
    const float* cls_b1  = (const float*)d_in[15];
    const float* prelu_a = (const float*)d_in[16];
    const float* cls_w2  = (const float*)d_in[17];
    const float* cls_b2  = (const float*)d_in[18];

    float* out = (float*)d_out;
    float* out_pred = out;                       // [50000, 2]
    float* out_z    = out + 100000;              // [50000, 128]
    float* out_avec = out + 100000 + NN * NHID;  // [1, 32, 128]
    float* out_alog = out_avec + NA * NHID;      // [32, 2]

    unsigned *p_tmp_s, *p_h_s, *p_xcA_s, *p_z_s, *p_ws;
    float *p_hx, *p_haB, *p_attn, *p_rowsum, *p_colsum;
    float *p_support, *p_U, *p_xcB, *p_t1;
    cudaGetSymbolAddress((void**)&p_tmp_s,   g_tmp_s);
    cudaGetSymbolAddress((void**)&p_h_s,     g_h_s);
    cudaGetSymbolAddress((void**)&p_xcA_s,   g_xcA_s);
    cudaGetSymbolAddress((void**)&p_z_s,     g_z_s);
    cudaGetSymbolAddress((void**)&p_ws,      g_ws);
    cudaGetSymbolAddress((void**)&p_hx,      g_hx);
    cudaGetSymbolAddress((void**)&p_haB,     g_haB);
    cudaGetSymbolAddress((void**)&p_attn,    g_attn);
    cudaGetSymbolAddress((void**)&p_rowsum,  g_rowsum);
    cudaGetSymbolAddress((void**)&p_colsum,  g_colsum);
    cudaGetSymbolAddress((void**)&p_support, g_support);
    cudaGetSymbolAddress((void**)&p_U,       g_U);
    cudaGetSymbolAddress((void**)&p_xcB,     g_xcB);
    cudaGetSymbolAddress((void**)&p_t1,      g_t1);

    const dim3 g1(1, NBLKS);
    cudaFuncSetAttribute(attn_kernel, cudaFuncAttributeMaxDynamicSharedMemorySize, 102400);

    // weight pre-split + anchor-side precomputes
    wprep_kernel<<<80, 128>>>(im_w1, im_w2, ml_w1, enc_w, cls_w1, p_ws);
    hab_kernel<<<dim3(NA, NP), NHID>>>(anchors, ml_w1, ml_b1, p_haB);
    anchor_kernel<<<1, 128>>>(anchors, cls_w1, cls_b1, prelu_a, cls_w2, cls_b2,
                              out_avec, out_alog);

    // input MLP: tmp = relu(x@W1+b1) [split out]; h = tmp@W2+b2 [split out]
    tgemm_kernel<1,0,1><<<g1, 512>>>(x, nullptr, p_ws, im_b1, nullptr,
                                     nullptr, p_tmp_s, NN, 16, NFEAT, 0, 0, 8);
    tgemm_kernel<0,1,1><<<g1, 512>>>(nullptr, p_tmp_s, p_ws + 16*2048, im_b2, nullptr,
                                     nullptr, p_h_s, NN, 8, 0, 0, 0, 8);

    // hx[p] = h @ Wx[p] -> fp32 interleaved [n][p*128+j]
    tgemm_kernel<0,1,0><<<dim3(NP, NBLKS), 512>>>(nullptr, p_h_s, p_ws + 24*2048,
                                                  nullptr, nullptr,
                                                  p_hx, nullptr, NN, 8, 0,
                                                  8*2048, NP*NHID, 0);

    cudaMemsetAsync(p_colsum, 0, NA * sizeof(float));
    attn_kernel<<<NN / 16, 256, 102400>>>(p_hx, p_haB, ml_w2, ml_b2,
                                          p_attn, p_rowsum, p_colsum);

    // 2-hop encoder
    // hop 0: support = h @ enc_w0 ; xcA (split)
    tgemm_kernel<0,1,0><<<g1, 512>>>(nullptr, p_h_s, p_ws + 56*2048, nullptr, nullptr,
                                     p_support, nullptr, NN, 8, 0, 0, NHID, 0);
    cudaMemsetAsync(p_U, 0, NA * NHID * sizeof(float));
    agg_kernel<<<(NN + 255) / 256, 256>>>(p_attn, p_support, p_U, NN);
    xc_kernel<1><<<(NN + 31) / 32, 128>>>(p_attn, p_rowsum, p_colsum, p_U,
                                          enc_b, nullptr, p_xcA_s, NN);
    // hop 1: support = xcA @ enc_w1 ; xcB (fp32)
    tgemm_kernel<0,1,0><<<g1, 512>>>(nullptr, p_xcA_s, p_ws + 64*2048, nullptr, nullptr,
                                     p_support, nullptr, NN, 8, 0, 0, NHID, 0);
    cudaMemsetAsync(p_U, 0, NA * NHID * sizeof(float));
    agg_kernel<<<(NN + 255) / 256, 256>>>(p_attn, p_support, p_U, NN);
    xc_kernel<0><<<(NN + 31) / 32, 128>>>(p_attn, p_rowsum, p_colsum, p_U,
                                          enc_b + NHID, p_xcB, nullptr, NN);

    // z = LN(xcB + h) -> out_z fp32 + z split ; classifier
    ln_kernel<<<NN / 8, 256>>>(p_xcB, p_h_s, ln_g, ln_b, out_z, p_z_s, NN);
    tgemm_kernel<2,1,0><<<g1, 512>>>(nullptr, p_z_s, p_ws + 72*2048, cls_b1, prelu_a,
                                     p_t1, nullptr, NN, 8, 0, 0, NHID, 0);
    pred_kernel<<<NN / 8, 256>>>(p_t1, cls_w2, cls_b2, out_pred, NN);
}